// round 16
// baseline (speedup 1.0000x reference)
#include <cuda_runtime.h>
#include <cuda_fp16.h>
#include <math.h>
#include <stdint.h>

// ---------------------------------------------------------------------------
// Problem constants
// ---------------------------------------------------------------------------
#define NB    8192      // batch
#define HID   1024
#define HEADS 8
#define ENCK  544       // 4*128 + 32
#define DECK  96
#define SDIM  512       // s columns
#define ADIM  128       // a columns
#define ACTN  32

// ---------------------------------------------------------------------------
// Scratch (device globals -- no runtime allocation allowed)
// ---------------------------------------------------------------------------
__device__ __align__(256) __half g_xenc [NB * ENCK];   // fp16(concat(s, a[:,:32]))
__device__ __align__(256) __half g_adec [NB * DECK];   // fp16(a[:, 32:])
__device__ __align__(256) __half g_enc  [NB * HID];    // enc_input (fp16)
__device__ __align__(256) __half g_dec  [NB * HID];    // dec_input (fp16)
__device__ __align__(256) __half g_h    [NB * HID];    // encoder_h (relu, fp16)
__device__ __align__(256) __half g_dH   [NB * HID];    // decoder_H (relu, fp16)
__device__ __align__(256) __half g_heads[HEADS * NB * HID]; // encoder_heads fp16
__device__ __align__(256) __half g_ctx  [NB * HID];    // context (fp16)
__device__ __align__(256) float  g_qpart[NB * 8];      // per-tile q partials
__device__ __align__(256) float  g_spart[HEADS * NB * 8]; // per-tile score partials
__device__ __align__(256) float  g_attnw[NB * HEADS];  // softmax weights

// fp16 weight copies
__device__ __align__(256) __half g_Wenc  [ENCK * HID];
__device__ __align__(256) __half g_Wdec  [DECK * HID];
__device__ __align__(256) __half g_Weh   [HID * HID];
__device__ __align__(256) __half g_Wheads[HEADS * HID * HID];
__device__ __align__(256) __half g_Wdh   [HID * HID];
__device__ __align__(256) __half g_W1    [HID * HID];

// ---------------------------------------------------------------------------
// Helpers
// ---------------------------------------------------------------------------
#define CP_ASYNC16(dst_u32, src_ptr) \
    asm volatile("cp.async.cg.shared.global [%0], [%1], 16;" \
                 :: "r"(dst_u32), "l"(src_ptr))
#define CP_COMMIT() asm volatile("cp.async.commit_group;")
#define CP_WAIT1()  asm volatile("cp.async.wait_group 1;")
#define CP_WAIT0()  asm volatile("cp.async.wait_group 0;")

// ---------------------------------------------------------------------------
// fp32 -> fp16 weight conversion, split: small weights vs W_heads (64 MB)
// ---------------------------------------------------------------------------
#define N4_ENC  (ENCK * HID / 4)
#define N4_DEC  (DECK * HID / 4)
#define N4_SQ   (HID * HID / 4)
#define N4_HEAD (HEADS * HID * HID / 4)
#define N4_SMALL (N4_ENC + N4_DEC + 3 * N4_SQ)

__global__ void cvt_wsmall_kernel(const float4* __restrict__ Wenc,
                                  const float4* __restrict__ Wdec,
                                  const float4* __restrict__ Weh,
                                  const float4* __restrict__ Wdh,
                                  const float4* __restrict__ W1)
{
    int i = blockIdx.x * blockDim.x + threadIdx.x;
    if (i >= N4_SMALL) return;

    const float4* src;
    __half2* dst;
    int j = i;
    if (j < N4_ENC)                    { src = Wenc; dst = (__half2*)g_Wenc; }
    else if ((j -= N4_ENC) < N4_DEC)   { src = Wdec; dst = (__half2*)g_Wdec; }
    else if ((j -= N4_DEC) < N4_SQ)    { src = Weh;  dst = (__half2*)g_Weh; }
    else if ((j -= N4_SQ)  < N4_SQ)    { src = Wdh;  dst = (__half2*)g_Wdh; }
    else    { j -= N4_SQ;                src = W1;   dst = (__half2*)g_W1; }

    float4 v = src[j];
    dst[2 * j]     = __floats2half2_rn(v.x, v.y);
    dst[2 * j + 1] = __floats2half2_rn(v.z, v.w);
}

__global__ void cvt_wheads_kernel(const float4* __restrict__ Wheads)
{
    int j = blockIdx.x * blockDim.x + threadIdx.x;
    if (j >= N4_HEAD) return;
    float4 v = Wheads[j];
    __half2* dst = (__half2*)g_Wheads;
    dst[2 * j]     = __floats2half2_rn(v.x, v.y);
    dst[2 * j + 1] = __floats2half2_rn(v.z, v.w);
}

// ---------------------------------------------------------------------------
// Concat + fp16 inputs
// ---------------------------------------------------------------------------
__global__ void concat_kernel(const float* __restrict__ s,
                              const float* __restrict__ a)
{
    int idx = blockIdx.x * blockDim.x + threadIdx.x;
    if (idx < NB * ENCK) {
        int b = idx / ENCK;
        int c = idx - b * ENCK;
        float v = (c < SDIM) ? s[(size_t)b * SDIM + c]
                             : a[(size_t)b * ADIM + (c - SDIM)];
        g_xenc[idx] = __float2half_rn(v);
    } else {
        int j = idx - NB * ENCK;
        if (j >= NB * DECK) return;
        int b = j / DECK;
        int c = j - b * DECK;
        g_adec[j] = __float2half_rn(a[(size_t)b * ADIM + ACTN + c]);
    }
}

// ---------------------------------------------------------------------------
// FP16 tensor-core GEMM: C[M,N] = act(A[M,K] @ W[K,N] + bias) -> fp16
// 128x128 block tile, BK=32, THREE-stage cp.async pipeline (one barrier per
// K-chunk), 8 warps each computing 64x32 via m16n8k16 mma.sync, 2 CTAs/SM.
// EPI=0: plain store.  EPI=1: q-fusion (dot rows with W2f -> qpart, no store).
// EPI=2: store + score-fusion (dot rows with dHp rows -> spart).
// ---------------------------------------------------------------------------
#define AS_STRIDE 40     // halves per A smem row (32 + 8 pad)
#define BS_STRIDE 136    // halves per B smem row (128 + 8 pad)
#define AS_BUF    (128 * AS_STRIDE)   // 5120 halves
#define BS_BUF    (32 * BS_STRIDE)    // 4352 halves
#define NSTAGE    3
#define SMEM_GEMM ((NSTAGE * AS_BUF + NSTAGE * BS_BUF) * 2)  // 56832 bytes

template <bool RELU, int EPI>
__global__ __launch_bounds__(256, 2)
void hgemm(const __half* __restrict__ A, int lda,
           const __half* __restrict__ W, size_t wstride,
           const float* __restrict__ bias, size_t bstride,
           __half* __restrict__ C, size_t cstride,
           int N, int K,
           const float* __restrict__ W2f,
           const __half* __restrict__ dHp,
           float* __restrict__ part)
{
    extern __shared__ __half smem[];

    const int tid    = threadIdx.x;
    const int lane   = tid & 31;
    const int wid    = tid >> 5;
    const int warp_m = wid >> 2;       // 0..1
    const int warp_n = wid & 3;        // 0..3
    const int bm = blockIdx.y * 128;
    const int bn = blockIdx.x * 128;
    const int z  = blockIdx.z;

    W    += (size_t)z * wstride;
    bias += (size_t)z * bstride;
    C    += (size_t)z * cstride;

    const uint32_t smem_u = (uint32_t)__cvta_generic_to_shared(smem);
    const uint32_t Bs_u   = smem_u + NSTAGE * AS_BUF * 2;

    const __half* Ag = A + (size_t)bm * lda;
    const __half* Wg = W + bn;

    float acc[4][4][4];
#pragma unroll
    for (int mt = 0; mt < 4; ++mt)
#pragma unroll
        for (int nt = 0; nt < 4; ++nt)
#pragma unroll
            for (int r = 0; r < 4; ++r) acc[mt][nt][r] = 0.f;

    const int S = K >> 5;   // stages of 32 (min here is 3)

    auto load_stage = [&](int s, int buf) {
        const int k0 = s << 5;
        const uint32_t abase = smem_u + (uint32_t)buf * AS_BUF * 2;
        const uint32_t bbase = Bs_u   + (uint32_t)buf * BS_BUF * 2;
#pragma unroll
        for (int j = 0; j < 2; ++j) {                 // A: 128 x 32 halves
            int i = tid + 256 * j;
            int r = i >> 2, c = (i & 3) << 3;
            CP_ASYNC16(abase + (uint32_t)(r * AS_STRIDE + c) * 2,
                       Ag + (size_t)r * lda + k0 + c);
        }
#pragma unroll
        for (int j = 0; j < 2; ++j) {                 // B: 32 x 128 halves
            int i = tid + 256 * j;
            int r = i >> 4, c = (i & 15) << 3;
            CP_ASYNC16(bbase + (uint32_t)(r * BS_STRIDE + c) * 2,
                       Wg + (size_t)(k0 + r) * N + c);
        }
        CP_COMMIT();
    };

    load_stage(0, 0);
    load_stage(1, 1);

    // ldmatrix lane geometry
    const int a_row  = lane & 15;
    const int a_col  = (lane >> 4) << 3;
    const int b_row4 = (lane & 7) + ((lane >> 3) & 1) * 8;
    const int b_csel = (lane >> 4);        // 0 or 1 -> nt, nt+1

    int buf = 0;
    for (int s = 0; s < S; ++s) {
        if (s + 1 < S) CP_WAIT1();
        else           CP_WAIT0();
        __syncthreads();

        if (s + 2 < S) {
            int nb = buf + 2; if (nb >= NSTAGE) nb -= NSTAGE;
            load_stage(s + 2, nb);
        }

        const uint32_t abase = smem_u + (uint32_t)buf * AS_BUF * 2;
        const uint32_t bbase = Bs_u   + (uint32_t)buf * BS_BUF * 2;

#pragma unroll
        for (int ks = 0; ks < 2; ++ks) {
            uint32_t afr[4][4];
#pragma unroll
            for (int mt = 0; mt < 4; ++mt) {
                uint32_t addr = abase +
                    (uint32_t)((warp_m * 64 + mt * 16 + a_row) * AS_STRIDE
                               + ks * 16 + a_col) * 2;
                asm volatile(
                    "ldmatrix.sync.aligned.m8n8.x4.shared.b16 "
                    "{%0,%1,%2,%3}, [%4];"
                    : "=r"(afr[mt][0]), "=r"(afr[mt][1]),
                      "=r"(afr[mt][2]), "=r"(afr[mt][3])
                    : "r"(addr));
            }
            uint32_t bfr[4][2];
#pragma unroll
            for (int np = 0; np < 2; ++np) {          // nt pairs {0,1},{2,3}
                int nt = np * 2;
                uint32_t addr = bbase +
                    (uint32_t)((ks * 16 + b_row4) * BS_STRIDE
                               + warp_n * 32 + (nt + b_csel) * 8) * 2;
                asm volatile(
                    "ldmatrix.sync.aligned.m8n8.x4.trans.shared.b16 "
                    "{%0,%1,%2,%3}, [%4];"
                    : "=r"(bfr[nt][0]), "=r"(bfr[nt][1]),
                      "=r"(bfr[nt + 1][0]), "=r"(bfr[nt + 1][1])
                    : "r"(addr));
            }
#pragma unroll
            for (int mt = 0; mt < 4; ++mt)
#pragma unroll
                for (int nt = 0; nt < 4; ++nt) {
                    asm volatile(
                        "mma.sync.aligned.m16n8k16.row.col.f32.f16.f16.f32 "
                        "{%0,%1,%2,%3},{%4,%5,%6,%7},{%8,%9},{%0,%1,%2,%3};"
                        : "+f"(acc[mt][nt][0]), "+f"(acc[mt][nt][1]),
                          "+f"(acc[mt][nt][2]), "+f"(acc[mt][nt][3])
                        : "r"(afr[mt][0]), "r"(afr[mt][1]),
                          "r"(afr[mt][2]), "r"(afr[mt][3]),
                          "r"(bfr[nt][0]), "r"(bfr[nt][1]));
                }
        }
        if (++buf >= NSTAGE) buf = 0;
    }

    // -- epilogue -----------------------------------------------------------
    float p0[4], p1[4];
    if (EPI != 0) {
#pragma unroll
        for (int mt = 0; mt < 4; ++mt) { p0[mt] = 0.f; p1[mt] = 0.f; }
    }
#pragma unroll
    for (int mt = 0; mt < 4; ++mt) {
        const int row0 = bm + warp_m * 64 + mt * 16 + (lane >> 2);
#pragma unroll
        for (int nt = 0; nt < 4; ++nt) {
            const int col = bn + warp_n * 32 + nt * 8 + 2 * (lane & 3);
            const float2 bv = *(const float2*)(bias + col);
            float2 v0, v1;
            v0.x = acc[mt][nt][0] + bv.x;
            v0.y = acc[mt][nt][1] + bv.y;
            v1.x = acc[mt][nt][2] + bv.x;
            v1.y = acc[mt][nt][3] + bv.y;
            if (RELU) {
                v0.x = fmaxf(v0.x, 0.f); v0.y = fmaxf(v0.y, 0.f);
                v1.x = fmaxf(v1.x, 0.f); v1.y = fmaxf(v1.y, 0.f);
            }
            if (EPI == 1) {
                const float2 w2v = *(const float2*)(W2f + col);
                p0[mt] += v0.x * w2v.x + v0.y * w2v.y;
                p1[mt] += v1.x * w2v.x + v1.y * w2v.y;
            } else {
                if (EPI == 2) {
                    float2 d0 = __half22float2(
                        *(const __half2*)(dHp + (size_t)row0 * HID + col));
                    float2 d1 = __half22float2(
                        *(const __half2*)(dHp + (size_t)(row0 + 8) * HID + col));
                    p0[mt] += v0.x * d0.x + v0.y * d0.y;
                    p1[mt] += v1.x * d1.x + v1.y * d1.y;
                }
                *(__half2*)(C + (size_t)row0 * N + col)       = __floats2half2_rn(v0.x, v0.y);
                *(__half2*)(C + (size_t)(row0 + 8) * N + col) = __floats2half2_rn(v1.x, v1.y);
            }
        }
        if (EPI != 0) {
#pragma unroll
            for (int o = 1; o < 4; o <<= 1) {
                p0[mt] += __shfl_xor_sync(0xffffffffu, p0[mt], o);
                p1[mt] += __shfl_xor_sync(0xffffffffu, p1[mt], o);
            }
        }
    }
    if (EPI != 0) {
        __syncthreads();                     // smem pipeline bufs now reusable
        float* sred = (float*)smem;          // [128 rows][4 warp_n]
        if ((lane & 3) == 0) {
            const int q = lane >> 2;         // 0..7
#pragma unroll
            for (int mt = 0; mt < 4; ++mt) {
                sred[(warp_m * 64 + mt * 16 + q)     * 4 + warp_n] = p0[mt];
                sred[(warp_m * 64 + mt * 16 + q + 8) * 4 + warp_n] = p1[mt];
            }
        }
        __syncthreads();
        if (tid < 128) {
            float sum = sred[tid * 4] + sred[tid * 4 + 1]
                      + sred[tid * 4 + 2] + sred[tid * 4 + 3];
            part[((size_t)z * NB + bm + tid) * 8 + blockIdx.x] = sum;
        }
    }
}

// ---------------------------------------------------------------------------
// softmax over fused score partials:  g_attnw[b,h] = softmax_h(sum_t spart)
// ---------------------------------------------------------------------------
__global__ void softmax_kernel()
{
    int b = blockIdx.x * blockDim.x + threadIdx.x;
    if (b >= NB) return;
    float sc[HEADS];
#pragma unroll
    for (int h = 0; h < HEADS; ++h) {
        const float* p = g_spart + ((size_t)h * NB + b) * 8;
        float s = 0.f;
#pragma unroll
        for (int i = 0; i < 8; ++i) s += p[i];
        sc[h] = s;
    }
    float m = sc[0];
#pragma unroll
    for (int h = 1; h < HEADS; ++h) m = fmaxf(m, sc[h]);
    float e[HEADS], sum = 0.f;
#pragma unroll
    for (int h = 0; h < HEADS; ++h) { e[h] = __expf(sc[h] - m); sum += e[h]; }
    float inv = 1.f / sum;
#pragma unroll
    for (int h = 0; h < HEADS; ++h) g_attnw[(size_t)b * HEADS + h] = e[h] * inv;
}

// ---------------------------------------------------------------------------
// context[b,d] = sum_h attnw[b,h] * heads[h,b,d]   (pure streaming, fp16 out)
// ---------------------------------------------------------------------------
__global__ __launch_bounds__(256)
void context_kernel()
{
    int t = blockIdx.x * blockDim.x + threadIdx.x;    // over NB*HID/8
    if (t >= NB * HID / 8) return;
    const int b  = t >> 7;                            // HID/8 = 128 per row
    const int d8 = t & 127;

    float w[HEADS];
#pragma unroll
    for (int h = 0; h < HEADS; ++h) w[h] = g_attnw[(size_t)b * HEADS + h];

    float acc[8];
#pragma unroll
    for (int k = 0; k < 8; ++k) acc[k] = 0.f;
#pragma unroll
    for (int h = 0; h < HEADS; ++h) {
        uint4 x = *(const uint4*)(g_heads + ((size_t)h * NB + b) * HID + d8 * 8);
        const __half2* xp = (const __half2*)&x;
#pragma unroll
        for (int j = 0; j < 4; ++j) {
            float2 f = __half22float2(xp[j]);
            acc[2 * j]     += f.x * w[h];
            acc[2 * j + 1] += f.y * w[h];
        }
    }
    __half2 hb[4];
#pragma unroll
    for (int j = 0; j < 4; ++j)
        hb[j] = __floats2half2_rn(acc[2 * j], acc[2 * j + 1]);
    *(uint4*)(g_ctx + (size_t)b * HID + d8 * 8) = *(uint4*)hb;
}

// ---------------------------------------------------------------------------
// out[b] = sum of 8 tile partials + b2   (fixed order, deterministic)
// ---------------------------------------------------------------------------
__global__ void final_sum_kernel(const float* __restrict__ b2,
                                 float* __restrict__ out)
{
    int b = blockIdx.x * blockDim.x + threadIdx.x;
    if (b >= NB) return;
    const float* p = g_qpart + (size_t)b * 8;
    float s = 0.f;
#pragma unroll
    for (int i = 0; i < 8; ++i) s += p[i];
    out[b] = s + b2[0];
}

// ---------------------------------------------------------------------------
// Launch (two-stream fork/join; stream+events created once, outside capture)
// ---------------------------------------------------------------------------
extern "C" void kernel_launch(void* const* d_in, const int* in_sizes, int n_in,
                              void* d_out, int out_size)
{
    const float* s        = (const float*)d_in[0];
    const float* a        = (const float*)d_in[1];
    const float* W_enc_in = (const float*)d_in[2];
    const float* b_enc_in = (const float*)d_in[3];
    const float* W_dec_in = (const float*)d_in[4];
    const float* b_dec_in = (const float*)d_in[5];
    const float* W_eh     = (const float*)d_in[6];
    const float* b_eh     = (const float*)d_in[7];
    const float* W_heads  = (const float*)d_in[8];
    const float* b_heads  = (const float*)d_in[9];
    const float* W_dh     = (const float*)d_in[10];
    const float* b_dh     = (const float*)d_in[11];
    const float* W1       = (const float*)d_in[12];
    const float* b1       = (const float*)d_in[13];
    const float* W2       = (const float*)d_in[14];
    const float* b2       = (const float*)d_in[15];
    float* out = (float*)d_out;

    __half *xenc, *adec, *enc, *dec, *h, *dH, *heads, *ctx;
    float  *qpart, *spart;
    __half *wenc, *wdec, *weh, *wheads, *wdh, *w1c;
    cudaGetSymbolAddress((void**)&xenc,   g_xenc);
    cudaGetSymbolAddress((void**)&adec,   g_adec);
    cudaGetSymbolAddress((void**)&enc,    g_enc);
    cudaGetSymbolAddress((void**)&dec,    g_dec);
    cudaGetSymbolAddress((void**)&h,      g_h);
    cudaGetSymbolAddress((void**)&dH,     g_dH);
    cudaGetSymbolAddress((void**)&heads,  g_heads);
    cudaGetSymbolAddress((void**)&ctx,    g_ctx);
    cudaGetSymbolAddress((void**)&qpart,  g_qpart);
    cudaGetSymbolAddress((void**)&spart,  g_spart);
    cudaGetSymbolAddress((void**)&wenc,   g_Wenc);
    cudaGetSymbolAddress((void**)&wdec,   g_Wdec);
    cudaGetSymbolAddress((void**)&weh,    g_Weh);
    cudaGetSymbolAddress((void**)&wheads, g_Wheads);
    cudaGetSymbolAddress((void**)&wdh,    g_Wdh);
    cudaGetSymbolAddress((void**)&w1c,    g_W1);

    cudaFuncSetAttribute(hgemm<false, 0>,
                         cudaFuncAttributeMaxDynamicSharedMemorySize, SMEM_GEMM);
    cudaFuncSetAttribute(hgemm<true, 0>,
                         cudaFuncAttributeMaxDynamicSharedMemorySize, SMEM_GEMM);
    cudaFuncSetAttribute(hgemm<true, 1>,
                         cudaFuncAttributeMaxDynamicSharedMemorySize, SMEM_GEMM);
    cudaFuncSetAttribute(hgemm<true, 2>,
                         cudaFuncAttributeMaxDynamicSharedMemorySize, SMEM_GEMM);

    struct Res {
        cudaStream_t s1;
        cudaEvent_t  ev[5];
        Res() {
            cudaStreamCreateWithFlags(&s1, cudaStreamNonBlocking);
            for (int i = 0; i < 5; ++i)
                cudaEventCreateWithFlags(&ev[i], cudaEventDisableTiming);
        }
    };
    static Res R;
    cudaStream_t s0 = 0;          // legacy default (capture) stream
    cudaStream_t s1 = R.s1;

    const dim3 gemm_grid(HID / 128, NB / 128, 1);       // 8 x 64
    const dim3 head_grid(HID / 128, NB / 128, HEADS);   // 8 x 64 x 8

    // fork
    cudaEventRecord(R.ev[0], s0);
    cudaStreamWaitEvent(s1, R.ev[0], 0);

    // s1: W_heads conversion (64 MB, no deps; overlaps the whole s0 prefix)
    cvt_wheads_kernel<<<(N4_HEAD + 255) / 256, 256, 0, s1>>>(
        (const float4*)W_heads);
    cudaEventRecord(R.ev[4], s1);          // wheads ready

    // s0: small weight conversion, then input concat
    cvt_wsmall_kernel<<<(N4_SMALL + 255) / 256, 256, 0, s0>>>(
        (const float4*)W_enc_in, (const float4*)W_dec_in, (const float4*)W_eh,
        (const float4*)W_dh, (const float4*)W1);
    concat_kernel<<<(NB * (ENCK + DECK) + 255) / 256, 256, 0, s0>>>(s, a);

    // s1 side branch (dec -> dH) needs wdec + adec from s0
    cudaEventRecord(R.ev[1], s0);
    cudaStreamWaitEvent(s1, R.ev[1], 0);

    // s0: enc -> eh                s1: dec -> dH
    hgemm<false, 0><<<gemm_grid, 256, SMEM_GEMM, s0>>>(
        xenc, ENCK, wenc, 0, b_enc_in, 0, enc, 0, HID, ENCK,
        nullptr, nullptr, nullptr);
    hgemm<false, 0><<<gemm_grid, 256, SMEM_GEMM, s1>>>(
        adec, DECK, wdec, 0, b_dec_in, 0, dec, 0, HID, DECK,
        nullptr, nullptr, nullptr);

    hgemm<true, 0><<<gemm_grid, 256, SMEM_GEMM, s0>>>(
        enc, HID, weh, 0, b_eh, 0, h, 0, HID, HID,
        nullptr, nullptr, nullptr);
    hgemm<true, 0><<<gemm_grid, 256, SMEM_GEMM, s1>>>(
        dec, HID, wdh, 0, b_dh, 0, dH, 0, HID, HID,
        nullptr, nullptr, nullptr);
    cudaEventRecord(R.ev[3], s1);          // dH ready

    // heads GEMM (score-fused epilogue) needs wheads AND dH
    cudaStreamWaitEvent(s0, R.ev[4], 0);
    cudaStreamWaitEvent(s0, R.ev[3], 0);
    hgemm<true, 2><<<head_grid, 256, SMEM_GEMM, s0>>>(
        h, HID, wheads, (size_t)HID * HID, b_heads, (size_t)HID,
        heads, (size_t)NB * HID, HID, HID,
        nullptr, dH, spart);

    // softmax over fused partials, then streaming context
    softmax_kernel<<<NB / 256, 256, 0, s0>>>();
    context_kernel<<<(NB * HID / 8) / 256, 256, 0, s0>>>();

    // fused: W1 GEMM + per-tile q partials (no x16 materialization)
    hgemm<true, 1><<<gemm_grid, 256, SMEM_GEMM, s0>>>(
        ctx, HID, w1c, 0, b1, 0, nullptr, 0, HID, HID,
        W2, nullptr, qpart);
    final_sum_kernel<<<NB / 256, 256, 0, s0>>>(b2, out);
}

// round 17
// speedup vs baseline: 1.1135x; 1.1135x over previous
#include <cuda_runtime.h>
#include <cuda_fp16.h>
#include <math.h>
#include <stdint.h>

// ---------------------------------------------------------------------------
// Problem constants
// ---------------------------------------------------------------------------
#define NB    8192      // batch
#define HID   1024
#define HEADS 8
#define ENCK  544       // 4*128 + 32
#define DECK  96
#define SDIM  512       // s columns
#define ADIM  128       // a columns
#define ACTN  32

// ---------------------------------------------------------------------------
// Scratch (device globals -- no runtime allocation allowed)
// ---------------------------------------------------------------------------
__device__ __align__(256) __half g_xenc [NB * ENCK];   // fp16(concat(s, a[:,:32]))
__device__ __align__(256) __half g_adec [NB * DECK];   // fp16(a[:, 32:])
__device__ __align__(256) __half g_enc  [NB * HID];    // enc_input (fp16)
__device__ __align__(256) __half g_dec  [NB * HID];    // dec_input (fp16)
__device__ __align__(256) __half g_h    [NB * HID];    // encoder_h (relu, fp16)
__device__ __align__(256) __half g_dH   [NB * HID];    // decoder_H (relu, fp16)
__device__ __align__(256) __half g_heads[HEADS * NB * HID]; // encoder_heads fp16
__device__ __align__(256) __half g_ctx  [NB * HID];    // context (fp16)
__device__ __align__(256) float  g_qpart[NB * 8];      // per-tile q partials

// fp16 weight copies
__device__ __align__(256) __half g_Wenc  [ENCK * HID];
__device__ __align__(256) __half g_Wdec  [DECK * HID];
__device__ __align__(256) __half g_Weh   [HID * HID];
__device__ __align__(256) __half g_Wheads[HEADS * HID * HID];
__device__ __align__(256) __half g_Wdh   [HID * HID];
__device__ __align__(256) __half g_W1    [HID * HID];

// ---------------------------------------------------------------------------
// Helpers
// ---------------------------------------------------------------------------
#define CP_ASYNC16(dst_u32, src_ptr) \
    asm volatile("cp.async.cg.shared.global [%0], [%1], 16;" \
                 :: "r"(dst_u32), "l"(src_ptr))
#define CP_COMMIT() asm volatile("cp.async.commit_group;")
#define CP_WAIT1()  asm volatile("cp.async.wait_group 1;")
#define CP_WAIT0()  asm volatile("cp.async.wait_group 0;")

// ---------------------------------------------------------------------------
// fp32 -> fp16 weight conversion, split: small weights vs W_heads (64 MB)
// ---------------------------------------------------------------------------
#define N4_ENC  (ENCK * HID / 4)
#define N4_DEC  (DECK * HID / 4)
#define N4_SQ   (HID * HID / 4)
#define N4_HEAD (HEADS * HID * HID / 4)
#define N4_SMALL (N4_ENC + N4_DEC + 3 * N4_SQ)

__global__ void cvt_wsmall_kernel(const float4* __restrict__ Wenc,
                                  const float4* __restrict__ Wdec,
                                  const float4* __restrict__ Weh,
                                  const float4* __restrict__ Wdh,
                                  const float4* __restrict__ W1)
{
    int i = blockIdx.x * blockDim.x + threadIdx.x;
    if (i >= N4_SMALL) return;

    const float4* src;
    __half2* dst;
    int j = i;
    if (j < N4_ENC)                    { src = Wenc; dst = (__half2*)g_Wenc; }
    else if ((j -= N4_ENC) < N4_DEC)   { src = Wdec; dst = (__half2*)g_Wdec; }
    else if ((j -= N4_DEC) < N4_SQ)    { src = Weh;  dst = (__half2*)g_Weh; }
    else if ((j -= N4_SQ)  < N4_SQ)    { src = Wdh;  dst = (__half2*)g_Wdh; }
    else    { j -= N4_SQ;                src = W1;   dst = (__half2*)g_W1; }

    float4 v = src[j];
    dst[2 * j]     = __floats2half2_rn(v.x, v.y);
    dst[2 * j + 1] = __floats2half2_rn(v.z, v.w);
}

__global__ void cvt_wheads_kernel(const float4* __restrict__ Wheads)
{
    int j = blockIdx.x * blockDim.x + threadIdx.x;
    if (j >= N4_HEAD) return;
    float4 v = Wheads[j];
    __half2* dst = (__half2*)g_Wheads;
    dst[2 * j]     = __floats2half2_rn(v.x, v.y);
    dst[2 * j + 1] = __floats2half2_rn(v.z, v.w);
}

// ---------------------------------------------------------------------------
// Concat + fp16 inputs
// ---------------------------------------------------------------------------
__global__ void concat_kernel(const float* __restrict__ s,
                              const float* __restrict__ a)
{
    int idx = blockIdx.x * blockDim.x + threadIdx.x;
    if (idx < NB * ENCK) {
        int b = idx / ENCK;
        int c = idx - b * ENCK;
        float v = (c < SDIM) ? s[(size_t)b * SDIM + c]
                             : a[(size_t)b * ADIM + (c - SDIM)];
        g_xenc[idx] = __float2half_rn(v);
    } else {
        int j = idx - NB * ENCK;
        if (j >= NB * DECK) return;
        int b = j / DECK;
        int c = j - b * DECK;
        g_adec[j] = __float2half_rn(a[(size_t)b * ADIM + ACTN + c]);
    }
}

// ---------------------------------------------------------------------------
// FP16 tensor-core GEMM: C[M,N] = act(A[M,K] @ W[K,N] + bias) -> fp16
// 128x128 block tile, BK=32, THREE-stage cp.async pipeline (one barrier per
// K-chunk), 8 warps each computing 64x32 via m16n8k16 mma.sync, 2 CTAs/SM.
// FUSE variant: instead of storing C, dot each output row's 128-col slice
// with W2 and emit one fp32 partial per (row, column-tile) to qpart.
// ---------------------------------------------------------------------------
#define AS_STRIDE 40     // halves per A smem row (32 + 8 pad)
#define BS_STRIDE 136    // halves per B smem row (128 + 8 pad)
#define AS_BUF    (128 * AS_STRIDE)   // 5120 halves
#define BS_BUF    (32 * BS_STRIDE)    // 4352 halves
#define NSTAGE    3
#define SMEM_GEMM ((NSTAGE * AS_BUF + NSTAGE * BS_BUF) * 2)  // 56832 bytes

template <bool RELU, bool FUSE>
__global__ __launch_bounds__(256, 2)
void hgemm(const __half* __restrict__ A, int lda,
           const __half* __restrict__ W, size_t wstride,
           const float* __restrict__ bias, size_t bstride,
           __half* __restrict__ C, size_t cstride,
           int N, int K,
           const float* __restrict__ W2f, float* __restrict__ qpart)
{
    extern __shared__ __half smem[];

    const int tid    = threadIdx.x;
    const int lane   = tid & 31;
    const int wid    = tid >> 5;
    const int warp_m = wid >> 2;       // 0..1
    const int warp_n = wid & 3;        // 0..3
    const int bm = blockIdx.y * 128;
    const int bn = blockIdx.x * 128;
    const int z  = blockIdx.z;

    W    += (size_t)z * wstride;
    bias += (size_t)z * bstride;
    C    += (size_t)z * cstride;

    const uint32_t smem_u = (uint32_t)__cvta_generic_to_shared(smem);
    const uint32_t Bs_u   = smem_u + NSTAGE * AS_BUF * 2;

    const __half* Ag = A + (size_t)bm * lda;
    const __half* Wg = W + bn;

    float acc[4][4][4];
#pragma unroll
    for (int mt = 0; mt < 4; ++mt)
#pragma unroll
        for (int nt = 0; nt < 4; ++nt)
#pragma unroll
            for (int r = 0; r < 4; ++r) acc[mt][nt][r] = 0.f;

    const int S = K >> 5;   // stages of 32 (min here is 3)

    auto load_stage = [&](int s, int buf) {
        const int k0 = s << 5;
        const uint32_t abase = smem_u + (uint32_t)buf * AS_BUF * 2;
        const uint32_t bbase = Bs_u   + (uint32_t)buf * BS_BUF * 2;
#pragma unroll
        for (int j = 0; j < 2; ++j) {                 // A: 128 x 32 halves
            int i = tid + 256 * j;
            int r = i >> 2, c = (i & 3) << 3;
            CP_ASYNC16(abase + (uint32_t)(r * AS_STRIDE + c) * 2,
                       Ag + (size_t)r * lda + k0 + c);
        }
#pragma unroll
        for (int j = 0; j < 2; ++j) {                 // B: 32 x 128 halves
            int i = tid + 256 * j;
            int r = i >> 4, c = (i & 15) << 3;
            CP_ASYNC16(bbase + (uint32_t)(r * BS_STRIDE + c) * 2,
                       Wg + (size_t)(k0 + r) * N + c);
        }
        CP_COMMIT();
    };

    load_stage(0, 0);
    load_stage(1, 1);

    // ldmatrix lane geometry
    const int a_row  = lane & 15;
    const int a_col  = (lane >> 4) << 3;
    const int b_row4 = (lane & 7) + ((lane >> 3) & 1) * 8;
    const int b_csel = (lane >> 4);        // 0 or 1 -> nt, nt+1

    int buf = 0;
    for (int s = 0; s < S; ++s) {
        if (s + 1 < S) CP_WAIT1();
        else           CP_WAIT0();
        __syncthreads();

        if (s + 2 < S) {
            int nb = buf + 2; if (nb >= NSTAGE) nb -= NSTAGE;
            load_stage(s + 2, nb);
        }

        const uint32_t abase = smem_u + (uint32_t)buf * AS_BUF * 2;
        const uint32_t bbase = Bs_u   + (uint32_t)buf * BS_BUF * 2;

#pragma unroll
        for (int ks = 0; ks < 2; ++ks) {
            uint32_t afr[4][4];
#pragma unroll
            for (int mt = 0; mt < 4; ++mt) {
                uint32_t addr = abase +
                    (uint32_t)((warp_m * 64 + mt * 16 + a_row) * AS_STRIDE
                               + ks * 16 + a_col) * 2;
                asm volatile(
                    "ldmatrix.sync.aligned.m8n8.x4.shared.b16 "
                    "{%0,%1,%2,%3}, [%4];"
                    : "=r"(afr[mt][0]), "=r"(afr[mt][1]),
                      "=r"(afr[mt][2]), "=r"(afr[mt][3])
                    : "r"(addr));
            }
            uint32_t bfr[4][2];
#pragma unroll
            for (int np = 0; np < 2; ++np) {          // nt pairs {0,1},{2,3}
                int nt = np * 2;
                uint32_t addr = bbase +
                    (uint32_t)((ks * 16 + b_row4) * BS_STRIDE
                               + warp_n * 32 + (nt + b_csel) * 8) * 2;
                asm volatile(
                    "ldmatrix.sync.aligned.m8n8.x4.trans.shared.b16 "
                    "{%0,%1,%2,%3}, [%4];"
                    : "=r"(bfr[nt][0]), "=r"(bfr[nt][1]),
                      "=r"(bfr[nt + 1][0]), "=r"(bfr[nt + 1][1])
                    : "r"(addr));
            }
#pragma unroll
            for (int mt = 0; mt < 4; ++mt)
#pragma unroll
                for (int nt = 0; nt < 4; ++nt) {
                    asm volatile(
                        "mma.sync.aligned.m16n8k16.row.col.f32.f16.f16.f32 "
                        "{%0,%1,%2,%3},{%4,%5,%6,%7},{%8,%9},{%0,%1,%2,%3};"
                        : "+f"(acc[mt][nt][0]), "+f"(acc[mt][nt][1]),
                          "+f"(acc[mt][nt][2]), "+f"(acc[mt][nt][3])
                        : "r"(afr[mt][0]), "r"(afr[mt][1]),
                          "r"(afr[mt][2]), "r"(afr[mt][3]),
                          "r"(bfr[nt][0]), "r"(bfr[nt][1]));
                }
        }
        if (++buf >= NSTAGE) buf = 0;
    }

    // -- epilogue -----------------------------------------------------------
    if (!FUSE) {
#pragma unroll
        for (int mt = 0; mt < 4; ++mt) {
            const int row0 = bm + warp_m * 64 + mt * 16 + (lane >> 2);
#pragma unroll
            for (int nt = 0; nt < 4; ++nt) {
                const int col = bn + warp_n * 32 + nt * 8 + 2 * (lane & 3);
                const float2 bv = *(const float2*)(bias + col);
                float2 v0, v1;
                v0.x = acc[mt][nt][0] + bv.x;
                v0.y = acc[mt][nt][1] + bv.y;
                v1.x = acc[mt][nt][2] + bv.x;
                v1.y = acc[mt][nt][3] + bv.y;
                if (RELU) {
                    v0.x = fmaxf(v0.x, 0.f); v0.y = fmaxf(v0.y, 0.f);
                    v1.x = fmaxf(v1.x, 0.f); v1.y = fmaxf(v1.y, 0.f);
                }
                *(__half2*)(C + (size_t)row0 * N + col)       = __floats2half2_rn(v0.x, v0.y);
                *(__half2*)(C + (size_t)(row0 + 8) * N + col) = __floats2half2_rn(v1.x, v1.y);
            }
        }
    } else {
        // Fused q-partial: p = sum over this tile's 128 cols of relu(x)*W2
        float p0[4], p1[4];
#pragma unroll
        for (int mt = 0; mt < 4; ++mt) { p0[mt] = 0.f; p1[mt] = 0.f; }
#pragma unroll
        for (int mt = 0; mt < 4; ++mt) {
#pragma unroll
            for (int nt = 0; nt < 4; ++nt) {
                const int col = bn + warp_n * 32 + nt * 8 + 2 * (lane & 3);
                const float2 bv  = *(const float2*)(bias + col);
                const float2 w2v = *(const float2*)(W2f + col);
                float2 v0, v1;
                v0.x = acc[mt][nt][0] + bv.x;
                v0.y = acc[mt][nt][1] + bv.y;
                v1.x = acc[mt][nt][2] + bv.x;
                v1.y = acc[mt][nt][3] + bv.y;
                if (RELU) {
                    v0.x = fmaxf(v0.x, 0.f); v0.y = fmaxf(v0.y, 0.f);
                    v1.x = fmaxf(v1.x, 0.f); v1.y = fmaxf(v1.y, 0.f);
                }
                p0[mt] += v0.x * w2v.x + v0.y * w2v.y;
                p1[mt] += v1.x * w2v.x + v1.y * w2v.y;
            }
            // reduce across the 4 lanes sharing each row (lane&3)
#pragma unroll
            for (int o = 1; o < 4; o <<= 1) {
                p0[mt] += __shfl_xor_sync(0xffffffffu, p0[mt], o);
                p1[mt] += __shfl_xor_sync(0xffffffffu, p1[mt], o);
            }
        }
        __syncthreads();                     // smem pipeline bufs now reusable
        float* sred = (float*)smem;          // [128 rows][4 warp_n]
        if ((lane & 3) == 0) {
            const int q = lane >> 2;         // 0..7
#pragma unroll
            for (int mt = 0; mt < 4; ++mt) {
                sred[(warp_m * 64 + mt * 16 + q)     * 4 + warp_n] = p0[mt];
                sred[(warp_m * 64 + mt * 16 + q + 8) * 4 + warp_n] = p1[mt];
            }
        }
        __syncthreads();
        if (tid < 128) {
            float sum = sred[tid * 4] + sred[tid * 4 + 1]
                      + sred[tid * 4 + 2] + sred[tid * 4 + 3];
            qpart[(size_t)(bm + tid) * 8 + blockIdx.x] = sum;
        }
    }
}

// ---------------------------------------------------------------------------
// Fused attention: one block (256 thr) per batch row. fp16 heads/dH.
// ---------------------------------------------------------------------------
__global__ __launch_bounds__(256)
void attn_fused_kernel()
{
    __shared__ uint4 sh[HEADS * HID / 8];   // 16 KB fp16 heads rows
    __shared__ float sattn[HEADS];

    const int b    = blockIdx.x;
    const int wid  = threadIdx.x >> 5;      // head index
    const int lane = threadIdx.x & 31;

    const uint4* eh  = (const uint4*)(g_heads + ((size_t)wid * NB + b) * HID);
    const uint4* dH8 = (const uint4*)(g_dH + (size_t)b * HID);
    uint4* shw = sh + wid * (HID / 8);

    float s = 0.f;
#pragma unroll
    for (int i = lane; i < HID / 8; i += 32) {   // 4 iters
        uint4 x = eh[i];
        uint4 y = dH8[i];
        shw[i] = x;
        const __half2* xp = (const __half2*)&x;
        const __half2* yp = (const __half2*)&y;
#pragma unroll
        for (int j = 0; j < 4; ++j) {
            float2 fx = __half22float2(xp[j]);
            float2 fy = __half22float2(yp[j]);
            s += fx.x * fy.x + fx.y * fy.y;
        }
    }
#pragma unroll
    for (int o = 16; o > 0; o >>= 1) s += __shfl_xor_sync(0xffffffffu, s, o);
    if (lane == 0) sattn[wid] = s;
    __syncthreads();

    if (threadIdx.x == 0) {
        float sc[HEADS];
#pragma unroll
        for (int h = 0; h < HEADS; ++h) sc[h] = sattn[h];
        float m = sc[0];
#pragma unroll
        for (int h = 1; h < HEADS; ++h) m = fmaxf(m, sc[h]);
        float e[HEADS], sum = 0.f;
#pragma unroll
        for (int h = 0; h < HEADS; ++h) { e[h] = __expf(sc[h] - m); sum += e[h]; }
        float inv = 1.f / sum;
#pragma unroll
        for (int h = 0; h < HEADS; ++h) sattn[h] = e[h] * inv;
    }
    __syncthreads();

    float w[HEADS];
#pragma unroll
    for (int h = 0; h < HEADS; ++h) w[h] = sattn[h];

    const int i = threadIdx.x;                    // half2 pair index
    const __half2* sh2 = (const __half2*)sh;
    float2 acc0 = make_float2(0.f, 0.f);
    float2 acc1 = make_float2(0.f, 0.f);
#pragma unroll
    for (int h = 0; h < HEADS; ++h) {
        float2 v0 = __half22float2(sh2[h * (HID / 2) + 2 * i]);
        float2 v1 = __half22float2(sh2[h * (HID / 2) + 2 * i + 1]);
        acc0.x += v0.x * w[h]; acc0.y += v0.y * w[h];
        acc1.x += v1.x * w[h]; acc1.y += v1.y * w[h];
    }
    __half2* dst = (__half2*)(g_ctx + (size_t)b * HID) + 2 * i;
    dst[0] = __floats2half2_rn(acc0.x, acc0.y);
    dst[1] = __floats2half2_rn(acc1.x, acc1.y);
}

// ---------------------------------------------------------------------------
// out[b] = sum of 8 tile partials + b2   (fixed order, deterministic)
// ---------------------------------------------------------------------------
__global__ void final_sum_kernel(const float* __restrict__ b2,
                                 float* __restrict__ out)
{
    int b = blockIdx.x * blockDim.x + threadIdx.x;
    if (b >= NB) return;
    const float* p = g_qpart + (size_t)b * 8;
    float s = 0.f;
#pragma unroll
    for (int i = 0; i < 8; ++i) s += p[i];
    out[b] = s + b2[0];
}

// ---------------------------------------------------------------------------
// Launch (two-stream fork/join; stream+events created once, outside capture)
// ---------------------------------------------------------------------------
extern "C" void kernel_launch(void* const* d_in, const int* in_sizes, int n_in,
                              void* d_out, int out_size)
{
    const float* s        = (const float*)d_in[0];
    const float* a        = (const float*)d_in[1];
    const float* W_enc_in = (const float*)d_in[2];
    const float* b_enc_in = (const float*)d_in[3];
    const float* W_dec_in = (const float*)d_in[4];
    const float* b_dec_in = (const float*)d_in[5];
    const float* W_eh     = (const float*)d_in[6];
    const float* b_eh     = (const float*)d_in[7];
    const float* W_heads  = (const float*)d_in[8];
    const float* b_heads  = (const float*)d_in[9];
    const float* W_dh     = (const float*)d_in[10];
    const float* b_dh     = (const float*)d_in[11];
    const float* W1       = (const float*)d_in[12];
    const float* b1       = (const float*)d_in[13];
    const float* W2       = (const float*)d_in[14];
    const float* b2       = (const float*)d_in[15];
    float* out = (float*)d_out;

    __half *xenc, *adec, *enc, *dec, *h, *dH, *heads, *ctx;
    float  *qpart;
    __half *wenc, *wdec, *weh, *wheads, *wdh, *w1c;
    cudaGetSymbolAddress((void**)&xenc,   g_xenc);
    cudaGetSymbolAddress((void**)&adec,   g_adec);
    cudaGetSymbolAddress((void**)&enc,    g_enc);
    cudaGetSymbolAddress((void**)&dec,    g_dec);
    cudaGetSymbolAddress((void**)&h,      g_h);
    cudaGetSymbolAddress((void**)&dH,     g_dH);
    cudaGetSymbolAddress((void**)&heads,  g_heads);
    cudaGetSymbolAddress((void**)&ctx,    g_ctx);
    cudaGetSymbolAddress((void**)&qpart,  g_qpart);
    cudaGetSymbolAddress((void**)&wenc,   g_Wenc);
    cudaGetSymbolAddress((void**)&wdec,   g_Wdec);
    cudaGetSymbolAddress((void**)&weh,    g_Weh);
    cudaGetSymbolAddress((void**)&wheads, g_Wheads);
    cudaGetSymbolAddress((void**)&wdh,    g_Wdh);
    cudaGetSymbolAddress((void**)&w1c,    g_W1);

    cudaFuncSetAttribute(hgemm<false, false>,
                         cudaFuncAttributeMaxDynamicSharedMemorySize, SMEM_GEMM);
    cudaFuncSetAttribute(hgemm<true, false>,
                         cudaFuncAttributeMaxDynamicSharedMemorySize, SMEM_GEMM);
    cudaFuncSetAttribute(hgemm<true, true>,
                         cudaFuncAttributeMaxDynamicSharedMemorySize, SMEM_GEMM);

    struct Res {
        cudaStream_t s1;
        cudaEvent_t  ev[6];
        Res() {
            cudaStreamCreateWithFlags(&s1, cudaStreamNonBlocking);
            for (int i = 0; i < 6; ++i)
                cudaEventCreateWithFlags(&ev[i], cudaEventDisableTiming);
        }
    };
    static Res R;
    cudaStream_t s0 = 0;          // legacy default (capture) stream
    cudaStream_t s1 = R.s1;

    const dim3 gemm_grid(HID / 128, NB / 128, 1);       // 8 x 64
    const dim3 head_grid(HID / 128, NB / 128, HEADS);   // 8 x 64 x 8

    // fork
    cudaEventRecord(R.ev[0], s0);
    cudaStreamWaitEvent(s1, R.ev[0], 0);

    // s1: input concat FIRST (so s0's enc GEMM unblocks ASAP), then W_heads cvt
    concat_kernel<<<(NB * (ENCK + DECK) + 255) / 256, 256, 0, s1>>>(s, a);
    cudaEventRecord(R.ev[2], s1);          // xenc/adec ready
    cvt_wheads_kernel<<<(N4_HEAD + 255) / 256, 256, 0, s1>>>(
        (const float4*)W_heads);
    cudaEventRecord(R.ev[4], s1);          // wheads ready

    // s0: small weight conversion (parallel with concat)
    cvt_wsmall_kernel<<<(N4_SMALL + 255) / 256, 256, 0, s0>>>(
        (const float4*)W_enc_in, (const float4*)W_dec_in, (const float4*)W_eh,
        (const float4*)W_dh, (const float4*)W1);
    cudaEventRecord(R.ev[1], s0);          // small weights ready

    // s0: enc -> eh (needs xenc from s1)
    cudaStreamWaitEvent(s0, R.ev[2], 0);
    hgemm<false, false><<<gemm_grid, 256, SMEM_GEMM, s0>>>(
        xenc, ENCK, wenc, 0, b_enc_in, 0, enc, 0, HID, ENCK, nullptr, nullptr);
    hgemm<true, false><<<gemm_grid, 256, SMEM_GEMM, s0>>>(
        enc, HID, weh, 0, b_eh, 0, h, 0, HID, HID, nullptr, nullptr);

    // s1: dec -> dH (needs wdec/wdh from s0's cvt_wsmall; adec in-order on s1)
    cudaStreamWaitEvent(s1, R.ev[1], 0);
    hgemm<false, false><<<gemm_grid, 256, SMEM_GEMM, s1>>>(
        adec, DECK, wdec, 0, b_dec_in, 0, dec, 0, HID, DECK, nullptr, nullptr);
    hgemm<true, false><<<gemm_grid, 256, SMEM_GEMM, s1>>>(
        dec, HID, wdh, 0, b_dh, 0, dH, 0, HID, HID, nullptr, nullptr);
    cudaEventRecord(R.ev[3], s1);          // dH ready

    // heads GEMM needs wheads (s1) in addition to h (s0)
    cudaStreamWaitEvent(s0, R.ev[4], 0);
    hgemm<true, false><<<head_grid, 256, SMEM_GEMM, s0>>>(
        h, HID, wheads, (size_t)HID * HID, b_heads, (size_t)HID,
        heads, (size_t)NB * HID, HID, HID, nullptr, nullptr);

    // join: attention needs heads (s0) and dH (s1)
    cudaStreamWaitEvent(s0, R.ev[3], 0);
    attn_fused_kernel<<<NB, 256, 0, s0>>>();

    // fused: W1 GEMM + per-tile q partials (no x16 materialization)
    hgemm<true, true><<<gemm_grid, 256, SMEM_GEMM, s0>>>(
        ctx, HID, w1c, 0, b1, 0, nullptr, 0, HID, HID, W2, qpart);
    final_sum_kernel<<<NB / 256, 256, 0, s0>>>(b2, out);
}